// round 13
// baseline (speedup 1.0000x reference)
#include <cuda_runtime.h>
#include <stdint.h>

#define NEG_FILL -1e20f
#define MAXB 8
#define MAXN 16384
#define CHS 32  // MAXN / 512

typedef unsigned long long u64;
typedef unsigned int u32;

// scratch (no allocation allowed); zero-initialized at module load.
// invariants restored before kernel exit: g_hist == 0, g_done == 0.
__device__ int g_topidx[MAXB * MAXN];
__device__ u32 g_hi[MAXB * MAXN];
__device__ u32 g_hist[MAXB * 4096];
__device__ u64 g_cand[MAXB * MAXN];
__device__ int g_done[MAXB];

__device__ __forceinline__ u32 mono32(float f) {
    u32 u = __float_as_uint(f);
    return (u & 0x80000000u) ? ~u : (u | 0x80000000u);
}
__device__ __forceinline__ float inv_mono32(u32 k) {
    u32 u = (k & 0x80000000u) ? (k ^ 0x80000000u) : ~k;
    return __uint_as_float(u);
}

// prob = max over tags 1..7 of softmax over 8 tags (num = max(e1..e7))
__device__ __forceinline__ float prob8v(float4 a, float4 b) {
    float m = fmaxf(fmaxf(fmaxf(a.x, a.y), fmaxf(a.z, a.w)),
                    fmaxf(fmaxf(b.x, b.y), fmaxf(b.z, b.w)));
    float e0 = expf(a.x - m);
    float e1 = expf(a.y - m), e2 = expf(a.z - m), e3 = expf(a.w - m);
    float e4 = expf(b.x - m), e5 = expf(b.y - m), e6 = expf(b.z - m);
    float e7 = expf(b.w - m);
    float num = fmaxf(fmaxf(fmaxf(e1, e2), fmaxf(e3, e4)),
                      fmaxf(fmaxf(e5, e6), e7));
    float z = ((e0 + e1) + (e2 + e3)) + ((e4 + e5) + (e6 + e7));
    return num / z;
}

// ---- block-wide inclusive scan, 512 threads (16 warps) ----
__device__ __forceinline__ int scan512(int v, int lane, int warp, int* s_w) {
    int acc = v;
    #pragma unroll
    for (int o = 1; o < 32; o <<= 1) {
        int x = __shfl_up_sync(0xFFFFFFFFu, acc, o);
        if (lane >= o) acc += x;
    }
    if (lane == 31) s_w[warp] = acc;
    __syncthreads();
    if (warp == 0) {
        int x = (lane < 16) ? s_w[lane] : 0;
        #pragma unroll
        for (int o = 1; o < 16; o <<= 1) {
            int y = __shfl_up_sync(0xFFFFFFFFu, x, o);
            if (lane >= o) x += y;
        }
        if (lane < 16) s_w[lane] = x;
    }
    __syncthreads();
    int res = acc + (warp ? s_w[warp - 1] : 0);
    __syncthreads();
    return res;
}

// dual crossing search in ONE packed scan (counts <= 16384 each; 512 thr)
__device__ __forceinline__ void find_digit2(const u32* hA, const u32* hB,
                                            int bins, int rA, int rB,
                                            int tid, int lane, int warp,
                                            int* s_w, int* s_bc) {
    int ipt = (bins + 511) >> 9;  // <= 8
    u32 la[8], lb[8];
    u32 lsum = 0;
    int base = bins - 1 - tid * ipt;
    #pragma unroll
    for (int k = 0; k < 8; ++k) {
        int bb = base - k;
        bool v = (k < ipt && bb >= 0);
        la[k] = v ? hA[bb] : 0u;
        lb[k] = v ? hB[bb] : 0u;
        lsum += (la[k] << 16) | lb[k];
    }
    u32 incl = (u32)scan512((int)lsum, lane, warp, s_w);
    u32 cum = incl - lsum;
    int cumA = (int)(cum >> 16), cumB = (int)(cum & 0xFFFFu);
    #pragma unroll
    for (int k = 0; k < 8; ++k) {
        int bb = base - k;
        if (k < ipt && bb >= 0) {
            if (cumA < rA && cumA + (int)la[k] >= rA) { s_bc[0] = bb; s_bc[1] = cumA; }
            cumA += (int)la[k];
            if (cumB < rB && cumB + (int)lb[k] >= rB) { s_bc[2] = bb; s_bc[3] = cumB; }
            cumB += (int)lb[k];
        }
    }
    __syncthreads();
}

// ---- Kernel 1: prob + keys + hist; last block per batch runs select ----
__global__ __launch_bounds__(512, 2) void prob_select(
    const float4* __restrict__ sa4, const float4* __restrict__ sb4,
    const void* __restrict__ mask, const int* __restrict__ seq_length,
    float* __restrict__ out, int B, int N, int K, int D, int BN)
{
    __shared__ u32 s_hist0[4096];
    __shared__ u32 s_hist1[4096];
    __shared__ int s_w[16];
    __shared__ int s_bc[4];
    __shared__ int s_cnt[2];
    __shared__ int s_fill;
    __shared__ int s_last;
    __shared__ u32 s_kmf;
    __shared__ unsigned s_byte;

    const int tid = threadIdx.x;
    const int lane = tid & 31;
    const int warp = tid >> 5;
    const int i0 = blockIdx.x * 512;
    const int b = i0 / N;  // 512 | N

    // ---- prob phase (identical math to best-known R11 per-element path) ----
    if (tid == 0) s_byte = 0;
    __syncthreads();
    const u32* w = (const u32*)mask;
    if (tid < 128) {
        u32 v = w[i0 / 4 + tid];
        if (v != 0u && v != 1u && v != 0x3F800000u) atomicOr(&s_byte, 1u);
    }
    __syncthreads();
    const bool isbyte = (s_byte != 0);
    const unsigned char* mb = (const unsigned char*)mask;

    int i = i0 + tid;
    bool ok = i < BN;
    u32 bin = 0;
    if (ok) {
        float pa = prob8v(__ldg(&sa4[2 * (size_t)i]), __ldg(&sa4[2 * (size_t)i + 1]));
        float pb = prob8v(__ldg(&sb4[2 * (size_t)i]), __ldg(&sb4[2 * (size_t)i + 1]));
        bool m = isbyte ? (mb[i] != 0) : (w[i] != 0u);
        u32 h = mono32(m ? fmaxf(pa, pb) : NEG_FILL);
        g_hi[i] = h;
        bin = h >> 20;
    }
    u32 msk = __ballot_sync(0xFFFFFFFFu, ok);
    if (ok) {
        u32 peers = __match_any_sync(msk, bin);
        if ((int)(__ffs(peers) - 1) == lane)
            atomicAdd(&g_hist[b * 4096 + bin], __popc(peers));
    }
    __threadfence();
    __syncthreads();

    // ---- arrival: last block of this batch becomes its select block ----
    if (tid == 0) {
        int bpB = N >> 9;
        int v = atomicAdd(&g_done[b], 1);
        s_last = (v == bpB - 1);
    }
    __syncthreads();
    if (!s_last) return;
    __threadfence();  // acquire: all batch writes visible (release was fence+atomic)

    // ================= SELECT for batch b (512 threads) =================
    const u32 Nm1 = (u32)(N - 1);
    int sl = seq_length[b];
    int num_keep = sl * 2;
    if (num_keep < 1) num_keep = 1;
    if (num_keep > K) num_keep = K;

    if (tid == 0) { s_fill = 0; s_cnt[0] = 0; s_cnt[1] = N; }
    __syncthreads();

    // level 0: both crossings from the global hist
    u32* gh_hist = g_hist + (size_t)b * 4096;
    int r0 = num_keep, r1 = K;
    find_digit2(gh_hist, gh_hist, 4096, r0, r1, tid, lane, warp, s_w, s_bc);
    u32 pfx0 = (u32)s_bc[0]; r0 -= s_bc[1];
    u32 pfx1 = (u32)s_bc[2]; r1 -= s_bc[3];
    bool sameb = (pfx0 == pfx1);
    for (int j = tid; j < 4096; j += 512) gh_hist[j] = 0;  // restore invariant
    __syncthreads();

    // single full-N pass: compact candidates of the threshold bins (global buf)
    const u32* ghi = g_hi + (size_t)b * N;
    u64* cb = g_cand + (size_t)b * MAXN;
    #pragma unroll 4
    for (int k = 0; k < CHS; ++k) {
        int ii = k * 512 + tid;
        u32 h = __ldcg(&ghi[ii]);
        u32 bn = h >> 20;
        u32 lo = Nm1 - (u32)ii;
        if (bn == pfx0) {
            int p = atomicAdd(&s_cnt[0], 1);
            cb[p] = (((u64)(h & 0xFFFFFu)) << 14) | lo;
        } else if (!sameb && bn == pfx1) {
            int p = atomicAdd(&s_cnt[1], -1);
            cb[p - 1] = (((u64)(h & 0xFFFFFu)) << 14) | lo;
        }
    }
    __syncthreads();
    const int c0 = s_cnt[0];
    const int c1 = sameb ? c0 : (N - s_cnt[1]);
    const u64* cd0 = cb;
    const u64* cd1 = sameb ? cb : (cb + s_cnt[1]);
    __syncthreads();

    // refine 34-bit candidate keys: 12 + 12 + 10 bits
    for (int j = tid; j < 4096; j += 512) { s_hist0[j] = 0; s_hist1[j] = 0; }
    __syncthreads();
    for (int ii = tid; ii < c0; ii += 512)
        atomicAdd(&s_hist0[(u32)(cd0[ii] >> 22)], 1u);
    if (!sameb)
        for (int ii = tid; ii < c1; ii += 512)
            atomicAdd(&s_hist1[(u32)(cd1[ii] >> 22)], 1u);
    __syncthreads();
    find_digit2(s_hist0, sameb ? s_hist0 : s_hist1, 4096, r0, r1,
                tid, lane, warp, s_w, s_bc);
    u32 a0 = (u32)s_bc[0]; r0 -= s_bc[1];
    u32 a1 = (u32)s_bc[2]; r1 -= s_bc[3];
    bool share = sameb && (a0 == a1);
    __syncthreads();

    for (int j = tid; j < 4096; j += 512) { s_hist0[j] = 0; s_hist1[j] = 0; }
    __syncthreads();
    for (int ii = tid; ii < c0; ii += 512) {
        u64 v = cd0[ii];
        if ((u32)(v >> 22) == a0) atomicAdd(&s_hist0[(u32)(v >> 10) & 4095u], 1u);
    }
    if (!share)
        for (int ii = tid; ii < c1; ii += 512) {
            u64 v = cd1[ii];
            if ((u32)(v >> 22) == a1) atomicAdd(&s_hist1[(u32)(v >> 10) & 4095u], 1u);
        }
    __syncthreads();
    find_digit2(s_hist0, share ? s_hist0 : s_hist1, 4096, r0, r1,
                tid, lane, warp, s_w, s_bc);
    u32 b0d = (u32)s_bc[0]; r0 -= s_bc[1];
    u32 b1d = (u32)s_bc[2]; r1 -= s_bc[3];
    share = share && (b0d == b1d);
    u32 pA0 = (a0 << 12) | b0d;
    u32 pA1 = (a1 << 12) | b1d;
    __syncthreads();

    for (int j = tid; j < 1024; j += 512) { s_hist0[j] = 0; s_hist1[j] = 0; }
    __syncthreads();
    for (int ii = tid; ii < c0; ii += 512) {
        u64 v = cd0[ii];
        if ((u32)(v >> 10) == pA0) atomicAdd(&s_hist0[(u32)v & 1023u], 1u);
    }
    if (!share)
        for (int ii = tid; ii < c1; ii += 512) {
            u64 v = cd1[ii];
            if ((u32)(v >> 10) == pA1) atomicAdd(&s_hist1[(u32)v & 1023u], 1u);
        }
    __syncthreads();
    find_digit2(s_hist0, share ? s_hist0 : s_hist1, 1024, r0, r1,
                tid, lane, warp, s_w, s_bc);
    u64 thr34_0 = ((u64)pA0 << 10) | (u32)s_bc[0];
    u64 thr34_1 = ((u64)pA1 << 10) | (u32)s_bc[2];

    const u32 hthr0 = (pfx0 << 20) | (u32)(thr34_0 >> 14);
    const u32 hthr1 = (pfx1 << 20) | (u32)(thr34_1 >> 14);
    const int imax0 = (int)(Nm1 - ((u32)thr34_0 & 0x3FFFu));
    const int imax1 = (int)(Nm1 - ((u32)thr34_1 & 0x3FFFu));
    __syncthreads();

    // pass A: ballots + counts + fill (re-read hi from L2)
    #pragma unroll 4
    for (int k = 0; k < CHS; ++k) {
        int ii = k * 512 + tid;
        u32 h = __ldcg(&ghi[ii]);
        bool p0 = (h > hthr0) || (h == hthr0 && ii <= imax0);
        bool p1 = (h > hthr1) || (h == hthr1 && ii <= imax1);
        u32 b0 = __ballot_sync(0xFFFFFFFFu, p0);
        u32 b1 = __ballot_sync(0xFFFFFFFFu, p1);
        if (lane == 0) {
            s_hist0[k * 16 + warp] = b0;
            s_hist1[k * 16 + warp] = (u32)__popc(b0);
            if (b1) atomicMax(&s_fill, k * 512 + warp * 32 + (31 - __clz(b1)));
        }
    }
    __syncthreads();
    {   // exclusive scan of the 512 per-(tile,warp) counts
        int v = (int)s_hist1[tid];
        int incl = scan512(v, lane, warp, s_w);
        s_hist1[tid] = (u32)(incl - v);
        __syncthreads();
    }
    int fill = s_fill;
    if (tid == (fill & 511)) s_kmf = __ldcg(&ghi[fill]);
    __syncthreads();

    // pass B: write outputs
    const u32 negk = mono32(NEG_FILL);
    float* idx_out = out;
    float* sc_out = out + (size_t)B * K * (1 + D);
    float* mk_out = sc_out + (size_t)B * K;
    int* gt = g_topidx + (size_t)b * N;
    const size_t obase = (size_t)b * K;

    #pragma unroll 4
    for (int k = 0; k < CHS; ++k) {
        int ii = k * 512 + tid;
        u32 bal = s_hist0[k * 16 + warp];
        if ((bal >> lane) & 1u) {
            int j = (int)s_hist1[k * 16 + warp]
                  + __popc(bal & ((1u << lane) - 1u));
            u32 h = __ldcg(&ghi[ii]);
            gt[j] = ii;
            idx_out[obase + j] = (float)ii;
            sc_out[obase + j] = inv_mono32(h);
            mk_out[obase + j] = (h != negk) ? 1.0f : 0.0f;
        }
    }
    u32 kmf = s_kmf;
    float scf = inv_mono32(kmf);
    for (int j = num_keep + tid; j < K; j += 512) {
        gt[j] = fill;
        idx_out[obase + j] = (float)fill;
        sc_out[obase + j] = scf;
        mk_out[obase + j] = 0.0f;
    }
    __syncthreads();
    if (tid == 0) g_done[b] = 0;  // restore invariant for next replay
}

// ---- Kernel 2: embedding gather (2 float4 per thread) ----
__global__ __launch_bounds__(256) void spanprune_gather(
    const float* __restrict__ emb, float* __restrict__ out_emb,
    int N, int D, int K, int total_pairs)
{
    int t = blockIdx.x * blockDim.x + threadIdx.x;
    if (t >= total_pairs) return;
    int ppr = D >> 3;  // float4-pairs per row
    int row = t / ppr;
    int c = (t - row * ppr) * 2;
    int b = row / K;
    int j = row - b * K;
    int idx = g_topidx[b * N + j];
    const float4* src = (const float4*)(emb + ((size_t)b * N + idx) * D);
    float4* dst = (float4*)(out_emb + (size_t)row * D);
    float4 v0 = __ldg(&src[c]);
    float4 v1 = __ldg(&src[c + 1]);
    __stcs(&dst[c], v0);
    __stcs(&dst[c + 1], v1);
}

extern "C" void kernel_launch(void* const* d_in, const int* in_sizes, int n_in,
                              void* d_out, int out_size)
{
    const float* emb = (const float*)d_in[0];
    const float4* sa = (const float4*)d_in[1];
    const float4* sb = (const float4*)d_in[2];
    const void* sm = d_in[3];
    const int* sl = (const int*)d_in[4];

    int B = in_sizes[4];                 // 8
    int BN = in_sizes[3];                // B*N
    int N = BN / B;                      // 16384
    int D = in_sizes[0] / BN;            // 256
    int K = out_size / (B * (D + 3));    // max_keep

    prob_select<<<(BN + 511) / 512, 512>>>(sa, sb, sm, sl, (float*)d_out,
                                           B, N, K, D, BN);

    int total_pairs = B * K * (D / 8);
    int threads = 256;
    int blocks = (total_pairs + threads - 1) / threads;
    spanprune_gather<<<blocks, threads>>>(emb, (float*)d_out + (size_t)B * K,
                                          N, D, K, total_pairs);
}

// round 14
// speedup vs baseline: 1.5308x; 1.5308x over previous
#include <cuda_runtime.h>
#include <stdint.h>

#define NEG_FILL -1e20f
#define MAXB 8
#define MAXN 16384
#define CH 16  // MAXN / 1024

typedef unsigned long long u64;
typedef unsigned int u32;
typedef unsigned short u16;

// scratch (no allocation allowed); zero-initialized at module load.
// g_hist invariant: zero at kernel_launch entry (select re-zeroes it).
__device__ int g_topidx[MAXB * MAXN];
__device__ u32 g_hi[MAXB * MAXN];
__device__ u32 g_hist[MAXB * 4096];

__device__ __forceinline__ u32 mono32(float f) {
    u32 u = __float_as_uint(f);
    return (u & 0x80000000u) ? ~u : (u | 0x80000000u);
}
__device__ __forceinline__ float inv_mono32(u32 k) {
    u32 u = (k & 0x80000000u) ? (k ^ 0x80000000u) : ~k;
    return __uint_as_float(u);
}

// prob = max over tags 1..7 of softmax over 8 tags (num = max(e1..e7))
__device__ __forceinline__ float prob8(const float4* p) {
    float4 a = p[0], b = p[1];
    float m = fmaxf(fmaxf(fmaxf(a.x, a.y), fmaxf(a.z, a.w)),
                    fmaxf(fmaxf(b.x, b.y), fmaxf(b.z, b.w)));
    float e0 = expf(a.x - m);
    float e1 = expf(a.y - m), e2 = expf(a.z - m), e3 = expf(a.w - m);
    float e4 = expf(b.x - m), e5 = expf(b.y - m), e6 = expf(b.z - m);
    float e7 = expf(b.w - m);
    float num = fmaxf(fmaxf(fmaxf(e1, e2), fmaxf(e3, e4)),
                      fmaxf(fmaxf(e5, e6), e7));
    float z = ((e0 + e1) + (e2 + e3)) + ((e4 + e5) + (e6 + e7));
    return num / z;
}

// ---- Kernel 1: mask detect + prob + hi keys + level-0 hist (R11 form) ----
__global__ __launch_bounds__(256) void prob_keys(
    const float4* __restrict__ sa4, const float4* __restrict__ sb4,
    const void* __restrict__ mask, int BN, int N)
{
    __shared__ unsigned s_byte;
    const int i0 = blockIdx.x * 256;
    const int tid = threadIdx.x;
    const int lane = tid & 31;
    if (tid == 0) s_byte = 0;
    __syncthreads();

    const u32* w = (const u32*)mask;
    if (tid < 64) {
        u32 v = w[i0 / 4 + tid];
        if (v != 0u && v != 1u && v != 0x3F800000u) atomicOr(&s_byte, 1u);
    }
    __syncthreads();
    const unsigned isbyte = s_byte;
    const unsigned char* mb = (const unsigned char*)mask;

    int i = i0 + tid;
    bool ok = i < BN;
    u32 bin = 0;
    int b = 0;
    if (ok) {
        float p = fmaxf(prob8((const float4*)&((const float4*)0)[0] + 0 == 0
                              ? sa4 + 2 * (size_t)i : sa4 + 2 * (size_t)i),
                        prob8(sb4 + 2 * (size_t)i));
        bool m = isbyte ? (mb[i] != 0) : (w[i] != 0u);
        u32 h = mono32(m ? p : NEG_FILL);
        g_hi[i] = h;
        bin = h >> 20;
        b = i / N;
    }
    u32 msk = __ballot_sync(0xFFFFFFFFu, ok);
    if (ok) {
        u32 peers = __match_any_sync(msk, bin);
        if ((int)(__ffs(peers) - 1) == lane)
            atomicAdd(&g_hist[b * 4096 + bin], __popc(peers));
    }
}

// ---- block-wide inclusive scan (1024 threads) ----
__device__ __forceinline__ int block_scan_incl(int v, int lane, int warp,
                                               int* s_w) {
    int acc = v;
    #pragma unroll
    for (int o = 1; o < 32; o <<= 1) {
        int x = __shfl_up_sync(0xFFFFFFFFu, acc, o);
        if (lane >= o) acc += x;
    }
    if (lane == 31) s_w[warp] = acc;
    __syncthreads();
    if (warp == 0) {
        int x = s_w[lane];
        #pragma unroll
        for (int o = 1; o < 32; o <<= 1) {
            int y = __shfl_up_sync(0xFFFFFFFFu, x, o);
            if (lane >= o) x += y;
        }
        s_w[lane] = x;
    }
    __syncthreads();
    int res = acc + (warp ? s_w[warp - 1] : 0);
    __syncthreads();
    return res;
}

// dual crossing search in ONE packed block scan (counts <= 16384 each)
__device__ __forceinline__ void find_digit2(const u32* hA, const u32* hB,
                                            int bins, int rA, int rB,
                                            int tid, int lane, int warp,
                                            int* s_w, int* s_bc) {
    int ipt = (bins + 1023) >> 10;  // <= 4
    u32 la[4], lb[4];
    u32 lsum = 0;
    int base = bins - 1 - tid * ipt;
    #pragma unroll
    for (int k = 0; k < 4; ++k) {
        int bb = base - k;
        bool v = (k < ipt && bb >= 0);
        la[k] = v ? hA[bb] : 0u;
        lb[k] = v ? hB[bb] : 0u;
        lsum += (la[k] << 16) | lb[k];
    }
    u32 incl = (u32)block_scan_incl((int)lsum, lane, warp, s_w);
    u32 cum = incl - lsum;
    int cumA = (int)(cum >> 16), cumB = (int)(cum & 0xFFFFu);
    #pragma unroll
    for (int k = 0; k < 4; ++k) {
        int bb = base - k;
        if (k < ipt && bb >= 0) {
            if (cumA < rA && cumA + (int)la[k] >= rA) { s_bc[0] = bb; s_bc[1] = cumA; }
            cumA += (int)la[k];
            if (cumB < rB && cumB + (int)lb[k] >= rB) { s_bc[2] = bb; s_bc[3] = cumB; }
            cumB += (int)lb[k];
        }
    }
    __syncthreads();
}

// dynamic smem: candidate 34-bit keys, N u64 (dual lists: front/back)
extern __shared__ u64 s_cand[];

__global__ __launch_bounds__(1024) void spanprune_select(
    const int* __restrict__ seq_length, float* __restrict__ out,
    int B, int N, int K, int D)
{
    __shared__ u32 s_hist0[4096];
    __shared__ u32 s_hist1[4096];
    __shared__ int s_w[32];
    __shared__ int s_bc[4];
    __shared__ int s_cnt[2];
    __shared__ int s_fill;
    __shared__ u32 s_kmf;

    const int b = blockIdx.x;
    const int tid = threadIdx.x;
    const int lane = tid & 31;
    const int warp = tid >> 5;
    const u32 Nm1 = (u32)(N - 1);

    int sl = seq_length[b];
    int num_keep = sl * 2;
    if (num_keep < 1) num_keep = 1;
    if (num_keep > K) num_keep = K;

    if (tid == 0) { s_fill = 0; s_cnt[0] = 0; s_cnt[1] = N; }

    // ---- level 0: both crossings from precomputed global hist ----
    u32* gh_hist = g_hist + (size_t)b * 4096;
    int r0 = num_keep, r1 = K;
    find_digit2(gh_hist, gh_hist, 4096, r0, r1, tid, lane, warp, s_w, s_bc);
    u32 pfx0 = (u32)s_bc[0]; r0 -= s_bc[1];
    u32 pfx1 = (u32)s_bc[2]; r1 -= s_bc[3];
    bool sameb = (pfx0 == pfx1);
    for (int j = tid; j < 4096; j += 1024) gh_hist[j] = 0;  // restore invariant
    __syncthreads();

    // ---- single full-N pass: hi -> registers, compact bin candidates ----
    const u32* ghi = g_hi + (size_t)b * N;
    u32 hreg[CH];
    #pragma unroll
    for (int k = 0; k < CH; ++k) {
        int i = k * 1024 + tid;
        u32 h = __ldg(&ghi[i]);
        hreg[k] = h;
        u32 bin = h >> 20;
        u32 lo = Nm1 - (u32)i;
        if (bin == pfx0) {
            int p = atomicAdd(&s_cnt[0], 1);
            s_cand[p] = (((u64)(h & 0xFFFFFu)) << 14) | lo;
        } else if (!sameb && bin == pfx1) {
            int p = atomicAdd(&s_cnt[1], -1);
            s_cand[p - 1] = (((u64)(h & 0xFFFFFu)) << 14) | lo;
        }
    }
    __syncthreads();
    const int c0 = s_cnt[0];
    const int c1 = sameb ? c0 : (N - s_cnt[1]);
    const u64* cd0 = s_cand;
    const u64* cd1 = sameb ? s_cand : (s_cand + s_cnt[1]);
    __syncthreads();

    // ---- refine 34-bit candidate keys: 12 + 12 + 10 bits ----
    for (int j = tid; j < 4096; j += 1024) { s_hist0[j] = 0; s_hist1[j] = 0; }
    __syncthreads();
    for (int i = tid; i < c0; i += 1024)
        atomicAdd(&s_hist0[(u32)(cd0[i] >> 22)], 1u);
    if (!sameb)
        for (int i = tid; i < c1; i += 1024)
            atomicAdd(&s_hist1[(u32)(cd1[i] >> 22)], 1u);
    __syncthreads();
    find_digit2(s_hist0, sameb ? s_hist0 : s_hist1, 4096, r0, r1,
                tid, lane, warp, s_w, s_bc);
    u32 a0 = (u32)s_bc[0]; r0 -= s_bc[1];
    u32 a1 = (u32)s_bc[2]; r1 -= s_bc[3];
    bool share = sameb && (a0 == a1);
    __syncthreads();

    for (int j = tid; j < 4096; j += 1024) { s_hist0[j] = 0; s_hist1[j] = 0; }
    __syncthreads();
    for (int i = tid; i < c0; i += 1024) {
        u64 v = cd0[i];
        if ((u32)(v >> 22) == a0) atomicAdd(&s_hist0[(u32)(v >> 10) & 4095u], 1u);
    }
    if (!share)
        for (int i = tid; i < c1; i += 1024) {
            u64 v = cd1[i];
            if ((u32)(v >> 22) == a1) atomicAdd(&s_hist1[(u32)(v >> 10) & 4095u], 1u);
        }
    __syncthreads();
    find_digit2(s_hist0, share ? s_hist0 : s_hist1, 4096, r0, r1,
                tid, lane, warp, s_w, s_bc);
    u32 b0d = (u32)s_bc[0]; r0 -= s_bc[1];
    u32 b1d = (u32)s_bc[2]; r1 -= s_bc[3];
    share = share && (b0d == b1d);
    u32 pA0 = (a0 << 12) | b0d;
    u32 pA1 = (a1 << 12) | b1d;
    __syncthreads();

    if (tid < 1024) { s_hist0[tid] = 0; s_hist1[tid] = 0; }
    __syncthreads();
    for (int i = tid; i < c0; i += 1024) {
        u64 v = cd0[i];
        if ((u32)(v >> 10) == pA0) atomicAdd(&s_hist0[(u32)v & 1023u], 1u);
    }
    if (!share)
        for (int i = tid; i < c1; i += 1024) {
            u64 v = cd1[i];
            if ((u32)(v >> 10) == pA1) atomicAdd(&s_hist1[(u32)v & 1023u], 1u);
        }
    __syncthreads();
    find_digit2(s_hist0, share ? s_hist0 : s_hist1, 1024, r0, r1,
                tid, lane, warp, s_w, s_bc);
    u64 thr34_0 = ((u64)pA0 << 10) | (u32)s_bc[0];
    u64 thr34_1 = ((u64)pA1 << 10) | (u32)s_bc[2];

    const u32 hthr0 = (pfx0 << 20) | (u32)(thr34_0 >> 14);
    const u32 hthr1 = (pfx1 << 20) | (u32)(thr34_1 >> 14);
    const int imax0 = (int)(Nm1 - ((u32)thr34_0 & 0x3FFFu));
    const int imax1 = (int)(Nm1 - ((u32)thr34_1 & 0x3FFFu));
    __syncthreads();

    // ---- pass A: ballots + counts + fill (from registers) ----
    #pragma unroll
    for (int k = 0; k < CH; ++k) {
        int i = k * 1024 + tid;
        u32 h = hreg[k];
        bool p0 = (h > hthr0) || (h == hthr0 && i <= imax0);
        bool p1 = (h > hthr1) || (h == hthr1 && i <= imax1);
        u32 b0 = __ballot_sync(0xFFFFFFFFu, p0);
        u32 b1 = __ballot_sync(0xFFFFFFFFu, p1);
        if (lane == 0) {
            s_hist0[k * 32 + warp] = b0;
            s_hist1[k * 32 + warp] = (u32)__popc(b0);
            if (b1) atomicMax(&s_fill, k * 1024 + warp * 32 + (31 - __clz(b1)));
        }
    }
    __syncthreads();
    {   // exclusive scan of the 512 per-(tile,warp) counts
        int v = (tid < CH * 32) ? (int)s_hist1[tid] : 0;
        int incl = block_scan_incl(v, lane, warp, s_w);
        if (tid < CH * 32) s_hist1[tid] = (u32)(incl - v);
    }
    int fill = s_fill;
    #pragma unroll
    for (int k = 0; k < CH; ++k)
        if (k * 1024 + tid == fill) s_kmf = hreg[k];
    __syncthreads();

    // ---- pass B: write outputs from registers (no syncs) ----
    const u32 negk = mono32(NEG_FILL);
    float* idx_out = out;
    float* sc_out = out + (size_t)B * K * (1 + D);
    float* mk_out = sc_out + (size_t)B * K;
    int* gt = g_topidx + (size_t)b * N;
    const size_t obase = (size_t)b * K;

    #pragma unroll
    for (int k = 0; k < CH; ++k) {
        int i = k * 1024 + tid;
        u32 bal = s_hist0[k * 32 + warp];
        if ((bal >> lane) & 1u) {
            int j = (int)s_hist1[k * 32 + warp]
                  + __popc(bal & ((1u << lane) - 1u));
            u32 h = hreg[k];
            gt[j] = i;
            idx_out[obase + j] = (float)i;
            sc_out[obase + j] = inv_mono32(h);
            mk_out[obase + j] = (h != negk) ? 1.0f : 0.0f;
        }
    }

    u32 kmf = s_kmf;
    float scf = inv_mono32(kmf);
    for (int j = num_keep + tid; j < K; j += 1024) {
        gt[j] = fill;
        idx_out[obase + j] = (float)fill;
        sc_out[obase + j] = scf;
        mk_out[obase + j] = 0.0f;
    }
}

// ---- Kernel 3: embedding gather — 2D grid, zero integer divisions ----
// blockIdx.y = batch; t = float4-pair index within batch; ppr shift = pprs.
__global__ __launch_bounds__(512) void spanprune_gather(
    const float* __restrict__ emb, float* __restrict__ out_emb,
    int N, int D, int K, int pprs, int pairs_per_batch)
{
    int t = blockIdx.x * blockDim.x + threadIdx.x;
    if (t >= pairs_per_batch) return;
    int b = blockIdx.y;
    int row = t >> pprs;                      // row within batch
    int c = (t & ((1 << pprs) - 1)) * 2;      // float4 column
    int idx = g_topidx[b * N + row];
    const float4* src = (const float4*)(emb + ((size_t)b * N + idx) * D);
    float4* dst = (float4*)(out_emb + ((size_t)b * K + row) * D);
    float4 v0 = __ldg(&src[c]);
    float4 v1 = __ldg(&src[c + 1]);
    __stcs(&dst[c], v0);
    __stcs(&dst[c + 1], v1);
}

extern "C" void kernel_launch(void* const* d_in, const int* in_sizes, int n_in,
                              void* d_out, int out_size)
{
    const float* emb = (const float*)d_in[0];
    const float4* sa = (const float4*)d_in[1];
    const float4* sb = (const float4*)d_in[2];
    const void* sm = d_in[3];
    const int* sl = (const int*)d_in[4];

    int B = in_sizes[4];                 // 8
    int BN = in_sizes[3];                // B*N
    int N = BN / B;                      // 16384
    int D = in_sizes[0] / BN;            // 256
    int K = out_size / (B * (D + 3));    // max_keep

    prob_keys<<<(BN + 255) / 256, 256>>>(sa, sb, sm, BN, N);

    size_t smem = (size_t)N * sizeof(u64);  // 128 KB candidate buffer
    cudaFuncSetAttribute(spanprune_select,
                         cudaFuncAttributeMaxDynamicSharedMemorySize,
                         (int)smem);
    spanprune_select<<<B, 1024, smem>>>(sl, (float*)d_out, B, N, K, D);

    // pairs-per-row = D/8 (power of two); shift amount
    int ppr = D / 8;
    int pprs = 0;
    while ((1 << pprs) < ppr) pprs++;
    int pairs_per_batch = K * ppr;
    dim3 ggrid((pairs_per_batch + 511) / 512, B);
    spanprune_gather<<<ggrid, 512>>>(emb, (float*)d_out + (size_t)B * K,
                                     N, D, K, pprs, pairs_per_batch);
}

// round 15
// speedup vs baseline: 1.5793x; 1.0317x over previous
#include <cuda_runtime.h>
#include <stdint.h>

#define NEG_FILL -1e20f
#define MAXB 8
#define MAXN 16384
#define CH 16  // MAXN / 1024

typedef unsigned long long u64;
typedef unsigned int u32;
typedef unsigned short u16;

// scratch (no allocation allowed); zero-initialized at module load.
// g_hist invariant: zero at kernel_launch entry (select re-zeroes it).
__device__ int g_topidx[MAXB * MAXN];
__device__ u32 g_hi[MAXB * MAXN];
__device__ u32 g_hist[MAXB * 4096];

__device__ __forceinline__ u32 mono32(float f) {
    u32 u = __float_as_uint(f);
    return (u & 0x80000000u) ? ~u : (u | 0x80000000u);
}
__device__ __forceinline__ float inv_mono32(u32 k) {
    u32 u = (k & 0x80000000u) ? (k ^ 0x80000000u) : ~k;
    return __uint_as_float(u);
}

// prob = max over tags 1..7 of softmax over 8 tags (num = max(e1..e7))
__device__ __forceinline__ float prob8(const float4* p) {
    float4 a = p[0], b = p[1];
    float m = fmaxf(fmaxf(fmaxf(a.x, a.y), fmaxf(a.z, a.w)),
                    fmaxf(fmaxf(b.x, b.y), fmaxf(b.z, b.w)));
    float e0 = expf(a.x - m);
    float e1 = expf(a.y - m), e2 = expf(a.z - m), e3 = expf(a.w - m);
    float e4 = expf(b.x - m), e5 = expf(b.y - m), e6 = expf(b.z - m);
    float e7 = expf(b.w - m);
    float num = fmaxf(fmaxf(fmaxf(e1, e2), fmaxf(e3, e4)),
                      fmaxf(fmaxf(e5, e6), e7));
    float z = ((e0 + e1) + (e2 + e3)) + ((e4 + e5) + (e6 + e7));
    return num / z;
}

// ---- Kernel 1: mask detect + prob + hi keys + level-0 hist (R11 form) ----
__global__ __launch_bounds__(256) void prob_keys(
    const float4* __restrict__ sa4, const float4* __restrict__ sb4,
    const void* __restrict__ mask, int BN, int N)
{
    __shared__ unsigned s_byte;
    const int i0 = blockIdx.x * 256;
    const int tid = threadIdx.x;
    const int lane = tid & 31;
    if (tid == 0) s_byte = 0;
    __syncthreads();

    const u32* w = (const u32*)mask;
    if (tid < 64) {
        u32 v = w[i0 / 4 + tid];
        if (v != 0u && v != 1u && v != 0x3F800000u) atomicOr(&s_byte, 1u);
    }
    __syncthreads();
    const unsigned isbyte = s_byte;
    const unsigned char* mb = (const unsigned char*)mask;

    int i = i0 + tid;
    bool ok = i < BN;
    u32 bin = 0;
    int b = 0;
    if (ok) {
        float p = fmaxf(prob8((const float4*)&((const float4*)0)[0] + 0 == 0
                              ? sa4 + 2 * (size_t)i : sa4 + 2 * (size_t)i),
                        prob8(sb4 + 2 * (size_t)i));
        bool m = isbyte ? (mb[i] != 0) : (w[i] != 0u);
        u32 h = mono32(m ? p : NEG_FILL);
        g_hi[i] = h;
        bin = h >> 20;
        b = i / N;
    }
    u32 msk = __ballot_sync(0xFFFFFFFFu, ok);
    if (ok) {
        u32 peers = __match_any_sync(msk, bin);
        if ((int)(__ffs(peers) - 1) == lane)
            atomicAdd(&g_hist[b * 4096 + bin], __popc(peers));
    }
}

// ---- block-wide inclusive scan (1024 threads) ----
__device__ __forceinline__ int block_scan_incl(int v, int lane, int warp,
                                               int* s_w) {
    int acc = v;
    #pragma unroll
    for (int o = 1; o < 32; o <<= 1) {
        int x = __shfl_up_sync(0xFFFFFFFFu, acc, o);
        if (lane >= o) acc += x;
    }
    if (lane == 31) s_w[warp] = acc;
    __syncthreads();
    if (warp == 0) {
        int x = s_w[lane];
        #pragma unroll
        for (int o = 1; o < 32; o <<= 1) {
            int y = __shfl_up_sync(0xFFFFFFFFu, x, o);
            if (lane >= o) x += y;
        }
        s_w[lane] = x;
    }
    __syncthreads();
    int res = acc + (warp ? s_w[warp - 1] : 0);
    __syncthreads();
    return res;
}

// dual crossing search in ONE packed block scan (counts <= 16384 each)
__device__ __forceinline__ void find_digit2(const u32* hA, const u32* hB,
                                            int bins, int rA, int rB,
                                            int tid, int lane, int warp,
                                            int* s_w, int* s_bc) {
    int ipt = (bins + 1023) >> 10;  // <= 4
    u32 la[4], lb[4];
    u32 lsum = 0;
    int base = bins - 1 - tid * ipt;
    #pragma unroll
    for (int k = 0; k < 4; ++k) {
        int bb = base - k;
        bool v = (k < ipt && bb >= 0);
        la[k] = v ? hA[bb] : 0u;
        lb[k] = v ? hB[bb] : 0u;
        lsum += (la[k] << 16) | lb[k];
    }
    u32 incl = (u32)block_scan_incl((int)lsum, lane, warp, s_w);
    u32 cum = incl - lsum;
    int cumA = (int)(cum >> 16), cumB = (int)(cum & 0xFFFFu);
    #pragma unroll
    for (int k = 0; k < 4; ++k) {
        int bb = base - k;
        if (k < ipt && bb >= 0) {
            if (cumA < rA && cumA + (int)la[k] >= rA) { s_bc[0] = bb; s_bc[1] = cumA; }
            cumA += (int)la[k];
            if (cumB < rB && cumB + (int)lb[k] >= rB) { s_bc[2] = bb; s_bc[3] = cumB; }
            cumB += (int)lb[k];
        }
    }
    __syncthreads();
}

// dynamic smem: candidate 34-bit keys, N u64 (dual lists: front/back)
extern __shared__ u64 s_cand[];

__global__ __launch_bounds__(1024) void spanprune_select(
    const int* __restrict__ seq_length, float* __restrict__ out,
    int B, int N, int K, int D)
{
    __shared__ u32 s_hist0[4096];
    __shared__ u32 s_hist1[4096];
    __shared__ int s_w[32];
    __shared__ int s_bc[4];
    __shared__ int s_cnt[2];
    __shared__ int s_fill;
    __shared__ u32 s_kmf;

    const int b = blockIdx.x;
    const int tid = threadIdx.x;
    const int lane = tid & 31;
    const int warp = tid >> 5;
    const u32 Nm1 = (u32)(N - 1);

    int sl = seq_length[b];
    int num_keep = sl * 2;
    if (num_keep < 1) num_keep = 1;
    if (num_keep > K) num_keep = K;

    if (tid == 0) { s_fill = 0; s_cnt[0] = 0; s_cnt[1] = N; }

    // ---- level 0: both crossings from precomputed global hist ----
    u32* gh_hist = g_hist + (size_t)b * 4096;
    int r0 = num_keep, r1 = K;
    find_digit2(gh_hist, gh_hist, 4096, r0, r1, tid, lane, warp, s_w, s_bc);
    u32 pfx0 = (u32)s_bc[0]; r0 -= s_bc[1];
    u32 pfx1 = (u32)s_bc[2]; r1 -= s_bc[3];
    bool sameb = (pfx0 == pfx1);
    for (int j = tid; j < 4096; j += 1024) gh_hist[j] = 0;  // restore invariant
    __syncthreads();

    // ---- single full-N pass: hi -> registers, compact bin candidates ----
    const u32* ghi = g_hi + (size_t)b * N;
    u32 hreg[CH];
    #pragma unroll
    for (int k = 0; k < CH; ++k) {
        int i = k * 1024 + tid;
        u32 h = __ldg(&ghi[i]);
        hreg[k] = h;
        u32 bin = h >> 20;
        u32 lo = Nm1 - (u32)i;
        if (bin == pfx0) {
            int p = atomicAdd(&s_cnt[0], 1);
            s_cand[p] = (((u64)(h & 0xFFFFFu)) << 14) | lo;
        } else if (!sameb && bin == pfx1) {
            int p = atomicAdd(&s_cnt[1], -1);
            s_cand[p - 1] = (((u64)(h & 0xFFFFFu)) << 14) | lo;
        }
    }
    __syncthreads();
    const int c0 = s_cnt[0];
    const int c1 = sameb ? c0 : (N - s_cnt[1]);
    const u64* cd0 = s_cand;
    const u64* cd1 = sameb ? s_cand : (s_cand + s_cnt[1]);
    __syncthreads();

    // ---- refine 34-bit candidate keys: 12 + 12 + 10 bits ----
    for (int j = tid; j < 4096; j += 1024) { s_hist0[j] = 0; s_hist1[j] = 0; }
    __syncthreads();
    for (int i = tid; i < c0; i += 1024)
        atomicAdd(&s_hist0[(u32)(cd0[i] >> 22)], 1u);
    if (!sameb)
        for (int i = tid; i < c1; i += 1024)
            atomicAdd(&s_hist1[(u32)(cd1[i] >> 22)], 1u);
    __syncthreads();
    find_digit2(s_hist0, sameb ? s_hist0 : s_hist1, 4096, r0, r1,
                tid, lane, warp, s_w, s_bc);
    u32 a0 = (u32)s_bc[0]; r0 -= s_bc[1];
    u32 a1 = (u32)s_bc[2]; r1 -= s_bc[3];
    bool share = sameb && (a0 == a1);
    __syncthreads();

    for (int j = tid; j < 4096; j += 1024) { s_hist0[j] = 0; s_hist1[j] = 0; }
    __syncthreads();
    for (int i = tid; i < c0; i += 1024) {
        u64 v = cd0[i];
        if ((u32)(v >> 22) == a0) atomicAdd(&s_hist0[(u32)(v >> 10) & 4095u], 1u);
    }
    if (!share)
        for (int i = tid; i < c1; i += 1024) {
            u64 v = cd1[i];
            if ((u32)(v >> 22) == a1) atomicAdd(&s_hist1[(u32)(v >> 10) & 4095u], 1u);
        }
    __syncthreads();
    find_digit2(s_hist0, share ? s_hist0 : s_hist1, 4096, r0, r1,
                tid, lane, warp, s_w, s_bc);
    u32 b0d = (u32)s_bc[0]; r0 -= s_bc[1];
    u32 b1d = (u32)s_bc[2]; r1 -= s_bc[3];
    share = share && (b0d == b1d);
    u32 pA0 = (a0 << 12) | b0d;
    u32 pA1 = (a1 << 12) | b1d;
    __syncthreads();

    if (tid < 1024) { s_hist0[tid] = 0; s_hist1[tid] = 0; }
    __syncthreads();
    for (int i = tid; i < c0; i += 1024) {
        u64 v = cd0[i];
        if ((u32)(v >> 10) == pA0) atomicAdd(&s_hist0[(u32)v & 1023u], 1u);
    }
    if (!share)
        for (int i = tid; i < c1; i += 1024) {
            u64 v = cd1[i];
            if ((u32)(v >> 10) == pA1) atomicAdd(&s_hist1[(u32)v & 1023u], 1u);
        }
    __syncthreads();
    find_digit2(s_hist0, share ? s_hist0 : s_hist1, 1024, r0, r1,
                tid, lane, warp, s_w, s_bc);
    u64 thr34_0 = ((u64)pA0 << 10) | (u32)s_bc[0];
    u64 thr34_1 = ((u64)pA1 << 10) | (u32)s_bc[2];

    const u32 hthr0 = (pfx0 << 20) | (u32)(thr34_0 >> 14);
    const u32 hthr1 = (pfx1 << 20) | (u32)(thr34_1 >> 14);
    const int imax0 = (int)(Nm1 - ((u32)thr34_0 & 0x3FFFu));
    const int imax1 = (int)(Nm1 - ((u32)thr34_1 & 0x3FFFu));
    __syncthreads();

    // ---- pass A: ballots + counts + fill (from registers) ----
    #pragma unroll
    for (int k = 0; k < CH; ++k) {
        int i = k * 1024 + tid;
        u32 h = hreg[k];
        bool p0 = (h > hthr0) || (h == hthr0 && i <= imax0);
        bool p1 = (h > hthr1) || (h == hthr1 && i <= imax1);
        u32 b0 = __ballot_sync(0xFFFFFFFFu, p0);
        u32 b1 = __ballot_sync(0xFFFFFFFFu, p1);
        if (lane == 0) {
            s_hist0[k * 32 + warp] = b0;
            s_hist1[k * 32 + warp] = (u32)__popc(b0);
            if (b1) atomicMax(&s_fill, k * 1024 + warp * 32 + (31 - __clz(b1)));
        }
    }
    __syncthreads();
    {   // exclusive scan of the 512 per-(tile,warp) counts
        int v = (tid < CH * 32) ? (int)s_hist1[tid] : 0;
        int incl = block_scan_incl(v, lane, warp, s_w);
        if (tid < CH * 32) s_hist1[tid] = (u32)(incl - v);
    }
    int fill = s_fill;
    #pragma unroll
    for (int k = 0; k < CH; ++k)
        if (k * 1024 + tid == fill) s_kmf = hreg[k];
    __syncthreads();

    // ---- pass B: write outputs from registers (no syncs) ----
    const u32 negk = mono32(NEG_FILL);
    float* idx_out = out;
    float* sc_out = out + (size_t)B * K * (1 + D);
    float* mk_out = sc_out + (size_t)B * K;
    int* gt = g_topidx + (size_t)b * N;
    const size_t obase = (size_t)b * K;

    #pragma unroll
    for (int k = 0; k < CH; ++k) {
        int i = k * 1024 + tid;
        u32 bal = s_hist0[k * 32 + warp];
        if ((bal >> lane) & 1u) {
            int j = (int)s_hist1[k * 32 + warp]
                  + __popc(bal & ((1u << lane) - 1u));
            u32 h = hreg[k];
            gt[j] = i;
            idx_out[obase + j] = (float)i;
            sc_out[obase + j] = inv_mono32(h);
            mk_out[obase + j] = (h != negk) ? 1.0f : 0.0f;
        }
    }

    u32 kmf = s_kmf;
    float scf = inv_mono32(kmf);
    for (int j = num_keep + tid; j < K; j += 1024) {
        gt[j] = fill;
        idx_out[obase + j] = (float)fill;
        sc_out[obase + j] = scf;
        mk_out[obase + j] = 0.0f;
    }
}

// ---- Kernel 3: embedding gather — 2D grid, zero integer divisions ----
// blockIdx.y = batch; t = float4-pair index within batch; ppr shift = pprs.
__global__ __launch_bounds__(512) void spanprune_gather(
    const float* __restrict__ emb, float* __restrict__ out_emb,
    int N, int D, int K, int pprs, int pairs_per_batch)
{
    int t = blockIdx.x * blockDim.x + threadIdx.x;
    if (t >= pairs_per_batch) return;
    int b = blockIdx.y;
    int row = t >> pprs;                      // row within batch
    int c = (t & ((1 << pprs) - 1)) * 2;      // float4 column
    int idx = g_topidx[b * N + row];
    const float4* src = (const float4*)(emb + ((size_t)b * N + idx) * D);
    float4* dst = (float4*)(out_emb + ((size_t)b * K + row) * D);
    float4 v0 = __ldg(&src[c]);
    float4 v1 = __ldg(&src[c + 1]);
    __stcs(&dst[c], v0);
    __stcs(&dst[c + 1], v1);
}

extern "C" void kernel_launch(void* const* d_in, const int* in_sizes, int n_in,
                              void* d_out, int out_size)
{
    const float* emb = (const float*)d_in[0];
    const float4* sa = (const float4*)d_in[1];
    const float4* sb = (const float4*)d_in[2];
    const void* sm = d_in[3];
    const int* sl = (const int*)d_in[4];

    int B = in_sizes[4];                 // 8
    int BN = in_sizes[3];                // B*N
    int N = BN / B;                      // 16384
    int D = in_sizes[0] / BN;            // 256
    int K = out_size / (B * (D + 3));    // max_keep

    prob_keys<<<(BN + 255) / 256, 256>>>(sa, sb, sm, BN, N);

    size_t smem = (size_t)N * sizeof(u64);  // 128 KB candidate buffer
    cudaFuncSetAttribute(spanprune_select,
                         cudaFuncAttributeMaxDynamicSharedMemorySize,
                         (int)smem);
    spanprune_select<<<B, 1024, smem>>>(sl, (float*)d_out, B, N, K, D);

    // pairs-per-row = D/8 (power of two); shift amount
    int ppr = D / 8;
    int pprs = 0;
    while ((1 << pprs) < ppr) pprs++;
    int pairs_per_batch = K * ppr;
    dim3 ggrid((pairs_per_batch + 511) / 512, B);
    spanprune_gather<<<ggrid, 512>>>(emb, (float*)d_out + (size_t)B * K,
                                     N, D, K, pprs, pairs_per_batch);
}